// round 6
// baseline (speedup 1.0000x reference)
#include <cuda_runtime.h>
#include <math.h>

#define NS 1024
#define NR 4096
#define TPB 256
#define SPLIT 4                       // blocks per sample
#define RB (NR / SPLIT)               // residues per block = 1024
#define RPT (RB / TPB)                // residues per thread = 4
#define NPART (NS * SPLIT)            // 4096 partial blocks
#define PRED_F4 (RB * 3 / 4)          // 768 float4 of pred per tile
#define PSTAGE (PRED_F4 / TPB)        // 3 float4 per thread (pred)

// ---------------- scratch (static device globals; no allocation) ----------------
__device__ __align__(16) float4 g_wt4[NR];   // (w*t_c0, w*t_c1, w*t_c2, w)
__device__ float g_stats[8];                 // [4]=1/Lt, [5]=1/d0^2
__device__ float g_Spart[NPART * 12];        // per-block partial: S(9), P(3)
__device__ float g_RT[NS * 12];              // per sample: R(9), c(3)
__device__ float g_tmpart[NPART];            // per-block partial TM sum

__device__ __forceinline__ float warpsum(float v) {
#pragma unroll
    for (int o = 16; o; o >>= 1) v += __shfl_down_sync(0xffffffffu, v, o);
    return v;
}

__device__ __forceinline__ float rcp_fast(float x) {
    float r;
    asm("rcp.approx.f32 %0, %1;" : "=f"(r) : "f"(x));
    return r;
}

// ---------------- kernel A: true-structure statistics + companion array ----------------
#define PRE_T 1024
__global__ void k_pre(const float* __restrict__ truec, const int* __restrict__ mask) {
    int tid = threadIdx.x;
    float ws = 0.f, wt0 = 0.f, wt1 = 0.f, wt2 = 0.f;
    for (int l = tid; l < NR; l += PRE_T) {
        float w = (mask[l] != 0) ? 1.0f : 0.0f;
        ws += w;
        wt0 += w * truec[l * 3 + 0];
        wt1 += w * truec[l * 3 + 1];
        wt2 += w * truec[l * 3 + 2];
    }
    __shared__ float sm[4][32];
    __shared__ float s_tm[3];
    int lane = tid & 31, wid = tid >> 5;
    ws = warpsum(ws); wt0 = warpsum(wt0); wt1 = warpsum(wt1); wt2 = warpsum(wt2);
    if (lane == 0) { sm[0][wid] = ws; sm[1][wid] = wt0; sm[2][wid] = wt1; sm[3][wid] = wt2; }
    __syncthreads();
    if (tid == 0) {
        float Lt = 0.f, a = 0.f, b = 0.f, c = 0.f;
        for (int i = 0; i < 32; i++) { Lt += sm[0][i]; a += sm[1][i]; b += sm[2][i]; c += sm[3][i]; }
        float inv = 1.0f / Lt;
        float m0 = a * inv, m1 = b * inv, m2 = c * inv;
        float d0 = (Lt <= 15.0f) ? 0.5f : (1.24f * cbrtf(Lt - 15.0f) - 1.8f);
        d0 = fmaxf(d0, 0.5f);
        g_stats[0] = m0; g_stats[1] = m1; g_stats[2] = m2;
        g_stats[3] = Lt; g_stats[4] = inv; g_stats[5] = 1.0f / (d0 * d0);
        s_tm[0] = m0; s_tm[1] = m1; s_tm[2] = m2;
    }
    __syncthreads();
    float m0 = s_tm[0], m1 = s_tm[1], m2 = s_tm[2];
    for (int l = tid; l < NR; l += PRE_T) {
        float w = (mask[l] != 0) ? 1.0f : 0.0f;
        float4 v;
        v.x = w * (truec[l * 3 + 0] - m0);
        v.y = w * (truec[l * 3 + 1] - m1);
        v.z = w * (truec[l * 3 + 2] - m2);
        v.w = w;
        g_wt4[l] = v;
    }
}

// ---------------- kernel B: partial covariance ----------------
// pred staged through smem (coalesced); wt4 front-batched straight to registers.
__global__ void __launch_bounds__(TPB, 4) k_cov(const float* __restrict__ pred) {
    __shared__ float s_pred[PRED_F4 * 4];
    __shared__ float red[12][8];

    int b = blockIdx.x;
    int s = b >> 2, q = b & 3;
    int tid = threadIdx.x;

    const float4* __restrict__ p4 =
        reinterpret_cast<const float4*>(pred + (size_t)s * NR * 3) + (size_t)q * PRED_F4;
    const float4* __restrict__ w4 = g_wt4 + q * RB;

    // front-batched loads: all 7 LDG.128 independent, no consumer until sync
    float4 tp0 = p4[tid];
    float4 tp1 = p4[tid + TPB];
    float4 tp2 = p4[tid + 2 * TPB];
    float4 tw0 = w4[tid];
    float4 tw1 = w4[tid + TPB];
    float4 tw2 = w4[tid + 2 * TPB];
    float4 tw3 = w4[tid + 3 * TPB];

    float4* st4 = reinterpret_cast<float4*>(s_pred);
    st4[tid] = tp0;
    st4[tid + TPB] = tp1;
    st4[tid + 2 * TPB] = tp2;
    __syncthreads();

    float S00 = 0, S01 = 0, S02 = 0, S10 = 0, S11 = 0, S12 = 0, S20 = 0, S21 = 0, S22 = 0;
    float P0 = 0, P1 = 0, P2 = 0;
    float4 tw[4] = {tw0, tw1, tw2, tw3};
#pragma unroll
    for (int k = 0; k < RPT; k++) {
        int l = tid + k * TPB;
        float px = s_pred[3 * l + 0];
        float py = s_pred[3 * l + 1];
        float pz = s_pred[3 * l + 2];
        float4 wt = tw[k];
        S00 = fmaf(px, wt.x, S00); S01 = fmaf(px, wt.y, S01); S02 = fmaf(px, wt.z, S02);
        S10 = fmaf(py, wt.x, S10); S11 = fmaf(py, wt.y, S11); S12 = fmaf(py, wt.z, S12);
        S20 = fmaf(pz, wt.x, S20); S21 = fmaf(pz, wt.y, S21); S22 = fmaf(pz, wt.z, S22);
        P0 = fmaf(wt.w, px, P0); P1 = fmaf(wt.w, py, P1); P2 = fmaf(wt.w, pz, P2);
    }

    int lane = tid & 31, wid = tid >> 5;
    float vals[12] = {S00, S01, S02, S10, S11, S12, S20, S21, S22, P0, P1, P2};
#pragma unroll
    for (int k = 0; k < 12; k++) {
        float v = warpsum(vals[k]);
        if (lane == 0) red[k][wid] = v;
    }
    __syncthreads();
    if (tid < 12) {
        float v = 0.f;
#pragma unroll
        for (int i = 0; i < 8; i++) v += red[tid][i];
        g_Spart[b * 12 + tid] = v;
    }
}

// ---------------- kernel C: reduce partials + Horn quaternion Kabsch ----------------
__global__ void k_rot() {
    int s = blockIdx.x * blockDim.x + threadIdx.x;
    if (s >= NS) return;

    float Sf[12];
#pragma unroll
    for (int i = 0; i < 12; i++) {
        float v = 0.f;
#pragma unroll
        for (int j = 0; j < SPLIT; j++) v += g_Spart[(s * SPLIT + j) * 12 + i];
        Sf[i] = v;
    }
    float Sxx = Sf[0], Sxy = Sf[1], Sxz = Sf[2];
    float Syx = Sf[3], Syy = Sf[4], Syz = Sf[5];
    float Szx = Sf[6], Szy = Sf[7], Szz = Sf[8];

    float A[4][4];
    A[0][0] = Sxx + Syy + Szz; A[0][1] = Syz - Szy;         A[0][2] = Szx - Sxz;         A[0][3] = Sxy - Syx;
    A[1][1] = Sxx - Syy - Szz; A[1][2] = Sxy + Syx;         A[1][3] = Szx + Sxz;
    A[2][2] = -Sxx + Syy - Szz; A[2][3] = Syz + Szy;
    A[3][3] = -Sxx - Syy + Szz;
    A[1][0] = A[0][1]; A[2][0] = A[0][2]; A[3][0] = A[0][3];
    A[2][1] = A[1][2]; A[3][1] = A[1][3]; A[3][2] = A[2][3];

    float V[4][4] = {{1, 0, 0, 0}, {0, 1, 0, 0}, {0, 0, 1, 0}, {0, 0, 0, 1}};

    for (int sweep = 0; sweep < 4; sweep++) {
#pragma unroll
        for (int p = 0; p < 3; p++) {
#pragma unroll
            for (int q = p + 1; q < 4; q++) {
                float apq = A[p][q];
                float scale = fabsf(A[p][p]) + fabsf(A[q][q]);
                if (fabsf(apq) > 1e-12f * scale + 1e-30f) {
                    float theta = (A[q][q] - A[p][p]) / (2.0f * apq);
                    float t = 1.0f / (fabsf(theta) + sqrtf(theta * theta + 1.0f));
                    if (theta < 0.0f) t = -t;
                    float cth = 1.0f / sqrtf(t * t + 1.0f);
                    float sth = t * cth;
#pragma unroll
                    for (int r = 0; r < 4; r++) {
                        float arp = A[r][p], arq = A[r][q];
                        A[r][p] = arp * cth - arq * sth;
                        A[r][q] = arp * sth + arq * cth;
                    }
#pragma unroll
                    for (int r = 0; r < 4; r++) {
                        float apr = A[p][r], aqr = A[q][r];
                        A[p][r] = apr * cth - aqr * sth;
                        A[q][r] = apr * sth + aqr * cth;
                    }
#pragma unroll
                    for (int r = 0; r < 4; r++) {
                        float vrp = V[r][p], vrq = V[r][q];
                        V[r][p] = vrp * cth - vrq * sth;
                        V[r][q] = vrp * sth + vrq * cth;
                    }
                }
            }
        }
    }

    int kk = 0;
    float best = A[0][0];
#pragma unroll
    for (int i = 1; i < 4; i++) if (A[i][i] > best) { best = A[i][i]; kk = i; }
    float q0 = V[0][kk], qx = V[1][kk], qy = V[2][kk], qz = V[3][kk];

    float R[3][3];
    R[0][0] = q0 * q0 + qx * qx - qy * qy - qz * qz;
    R[0][1] = 2.0f * (qx * qy - q0 * qz);
    R[0][2] = 2.0f * (qx * qz + q0 * qy);
    R[1][0] = 2.0f * (qy * qx + q0 * qz);
    R[1][1] = q0 * q0 - qx * qx + qy * qy - qz * qz;
    R[1][2] = 2.0f * (qy * qz - q0 * qx);
    R[2][0] = 2.0f * (qz * qx - q0 * qy);
    R[2][1] = 2.0f * (qz * qy + q0 * qx);
    R[2][2] = q0 * q0 - qx * qx - qy * qy + qz * qz;

    // orientation safeguard
    float Sm[3][3] = {{Sxx, Sxy, Sxz}, {Syx, Syy, Syz}, {Szx, Szy, Szz}};
    float obj = 0.f, objT = 0.f;
#pragma unroll
    for (int i = 0; i < 3; i++)
#pragma unroll
        for (int j = 0; j < 3; j++) {
            obj  += R[i][j] * Sm[j][i];
            objT += R[j][i] * Sm[j][i];
        }
    if (objT > obj) {
#pragma unroll
        for (int i = 0; i < 3; i++)
#pragma unroll
            for (int j = i + 1; j < 3; j++) {
                float tmp = R[i][j]; R[i][j] = R[j][i]; R[j][i] = tmp;
            }
    }

    float invLt = g_stats[4];
    float pm0 = Sf[9] * invLt, pm1 = Sf[10] * invLt, pm2 = Sf[11] * invLt;
    int base = s * 12;
    g_RT[base + 0] = R[0][0]; g_RT[base + 1] = R[0][1]; g_RT[base + 2] = R[0][2];
    g_RT[base + 3] = R[1][0]; g_RT[base + 4] = R[1][1]; g_RT[base + 5] = R[1][2];
    g_RT[base + 6] = R[2][0]; g_RT[base + 7] = R[2][1]; g_RT[base + 8] = R[2][2];
    g_RT[base + 9]  = R[0][0] * pm0 + R[0][1] * pm1 + R[0][2] * pm2;
    g_RT[base + 10] = R[1][0] * pm0 + R[1][1] * pm1 + R[1][2] * pm2;
    g_RT[base + 11] = R[2][0] * pm0 + R[2][1] * pm1 + R[2][2] * pm2;
}

// ---------------- kernel D: partial TM sums ----------------
__global__ void __launch_bounds__(TPB, 4) k_tm(const float* __restrict__ pred) {
    __shared__ float s_pred[PRED_F4 * 4];
    __shared__ float P[16];
    __shared__ float red[8];

    int b = blockIdx.x;
    int s = b >> 2, q = b & 3;
    int tid = threadIdx.x;

    if (tid < 12) P[tid] = g_RT[s * 12 + tid];
    if (tid == 12) P[12] = g_stats[5];

    const float4* __restrict__ p4 =
        reinterpret_cast<const float4*>(pred + (size_t)s * NR * 3) + (size_t)q * PRED_F4;
    const float4* __restrict__ w4 = g_wt4 + q * RB;

    float4 tp0 = p4[tid];
    float4 tp1 = p4[tid + TPB];
    float4 tp2 = p4[tid + 2 * TPB];
    float4 tw0 = w4[tid];
    float4 tw1 = w4[tid + TPB];
    float4 tw2 = w4[tid + 2 * TPB];
    float4 tw3 = w4[tid + 3 * TPB];

    float4* st4 = reinterpret_cast<float4*>(s_pred);
    st4[tid] = tp0;
    st4[tid + TPB] = tp1;
    st4[tid + 2 * TPB] = tp2;
    __syncthreads();

    float R00 = P[0], R01 = P[1], R02 = P[2];
    float R10 = P[3], R11 = P[4], R12 = P[5];
    float R20 = P[6], R21 = P[7], R22 = P[8];
    float c0 = P[9], c1 = P[10], c2 = P[11];
    float invd0 = P[12];

    float acc = 0.f;
    float4 tw[4] = {tw0, tw1, tw2, tw3};
#pragma unroll
    for (int k = 0; k < RPT; k++) {
        int l = tid + k * TPB;
        float px = s_pred[3 * l + 0];
        float py = s_pred[3 * l + 1];
        float pz = s_pred[3 * l + 2];
        float4 wt = tw[k];
        float dx = fmaf(R00, px, fmaf(R01, py, fmaf(R02, pz, -c0))) - wt.x;
        float dy = fmaf(R10, px, fmaf(R11, py, fmaf(R12, pz, -c1))) - wt.y;
        float dz = fmaf(R20, px, fmaf(R21, py, fmaf(R22, pz, -c2))) - wt.z;
        float dsq = fmaf(dx, dx, fmaf(dy, dy, dz * dz));
        acc += wt.w * rcp_fast(fmaf(dsq, invd0, 1.0f));
    }

    int lane = tid & 31, wid = tid >> 5;
    acc = warpsum(acc);
    if (lane == 0) red[wid] = acc;
    __syncthreads();
    if (tid == 0) {
        float v = 0.f;
#pragma unroll
        for (int i = 0; i < 8; i++) v += red[i];
        g_tmpart[b] = v;
    }
}

// ---------------- kernel E: final reduction ----------------
__global__ void k_final(float* __restrict__ out) {
    int s = blockIdx.x * blockDim.x + threadIdx.x;
    if (s >= NS) return;
    float invLt = g_stats[4];
    float v = g_tmpart[s * SPLIT + 0] + g_tmpart[s * SPLIT + 1]
            + g_tmpart[s * SPLIT + 2] + g_tmpart[s * SPLIT + 3];
    out[s] = v * invLt;
}

// ---------------- launch ----------------
extern "C" void kernel_launch(void* const* d_in, const int* in_sizes, int n_in,
                              void* d_out, int out_size) {
    const float* pred = (const float*)d_in[0];
    const float* truec = (const float*)d_in[1];
    const int* mask = (const int*)d_in[2];
    float* out = (float*)d_out;

    k_pre<<<1, PRE_T>>>(truec, mask);
    k_cov<<<NPART, TPB>>>(pred);
    k_rot<<<4, 256>>>();
    k_tm<<<NPART, TPB>>>(pred);
    k_final<<<4, 256>>>(out);
}

// round 7
// speedup vs baseline: 1.4058x; 1.4058x over previous
#include <cuda_runtime.h>
#include <math.h>

#define NS 1024
#define NR 4096
#define TPB 256
#define NB 4                          // batches per thread (4 residues each)

// ---------------- scratch (static device globals; no allocation) ----------------
__device__ __align__(16) float g_wt3[NR * 3];  // w*(t-mean), layout mirrors pred
__device__ __align__(16) float g_wf[NR];       // w per residue
__device__ float g_stats[8];                   // [4]=1/Lt, [5]=1/d0^2
__device__ float g_S[NS * 12];                 // per sample: S(9), P(3)
__device__ float g_RT[NS * 12];                // per sample: R(9), c(3)

__device__ __forceinline__ float warpsum(float v) {
#pragma unroll
    for (int o = 16; o; o >>= 1) v += __shfl_down_sync(0xffffffffu, v, o);
    return v;
}

__device__ __forceinline__ float rcp_fast(float x) {
    float r;
    asm("rcp.approx.f32 %0, %1;" : "=f"(r) : "f"(x));
    return r;
}

struct Batch {
    float4 p0, p1, p2;   // 4 residues of pred (12 floats)
    float4 t0, t1, t2;   // matching w*t_c (12 floats)
    float4 w;            // 4 weights
};

// batch b, thread tid: pred f4s [b*768+3*tid .. +2], wf f4 [b*256+tid]
#define LOADB(B_, b_) do { \
    int o3 = (b_) * 768 + 3 * tid; \
    (B_).p0 = p4[o3]; (B_).p1 = p4[o3 + 1]; (B_).p2 = p4[o3 + 2]; \
    (B_).t0 = t4[o3]; (B_).t1 = t4[o3 + 1]; (B_).t2 = t4[o3 + 2]; \
    (B_).w  = w4[(b_) * 256 + tid]; } while (0)

// ---------------- kernel A: true stats + wt3/wf companions ----------------
#define PRE_T 1024
__global__ void k_pre(const float* __restrict__ truec, const int* __restrict__ mask) {
    int tid = threadIdx.x;
    float ws = 0.f, wt0 = 0.f, wt1 = 0.f, wt2 = 0.f;
    for (int l = tid; l < NR; l += PRE_T) {
        float w = (mask[l] != 0) ? 1.0f : 0.0f;
        ws += w;
        wt0 += w * truec[l * 3 + 0];
        wt1 += w * truec[l * 3 + 1];
        wt2 += w * truec[l * 3 + 2];
    }
    __shared__ float sm[4][32];
    __shared__ float s_tm[3];
    int lane = tid & 31, wid = tid >> 5;
    ws = warpsum(ws); wt0 = warpsum(wt0); wt1 = warpsum(wt1); wt2 = warpsum(wt2);
    if (lane == 0) { sm[0][wid] = ws; sm[1][wid] = wt0; sm[2][wid] = wt1; sm[3][wid] = wt2; }
    __syncthreads();
    if (tid == 0) {
        float Lt = 0.f, a = 0.f, b = 0.f, c = 0.f;
        for (int i = 0; i < 32; i++) { Lt += sm[0][i]; a += sm[1][i]; b += sm[2][i]; c += sm[3][i]; }
        float inv = 1.0f / Lt;
        float m0 = a * inv, m1 = b * inv, m2 = c * inv;
        float d0 = (Lt <= 15.0f) ? 0.5f : (1.24f * cbrtf(Lt - 15.0f) - 1.8f);
        d0 = fmaxf(d0, 0.5f);
        g_stats[0] = m0; g_stats[1] = m1; g_stats[2] = m2;
        g_stats[3] = Lt; g_stats[4] = inv; g_stats[5] = 1.0f / (d0 * d0);
        s_tm[0] = m0; s_tm[1] = m1; s_tm[2] = m2;
    }
    __syncthreads();
    float m0 = s_tm[0], m1 = s_tm[1], m2 = s_tm[2];
    for (int l = tid; l < NR; l += PRE_T) {
        float w = (mask[l] != 0) ? 1.0f : 0.0f;
        g_wt3[l * 3 + 0] = w * (truec[l * 3 + 0] - m0);
        g_wt3[l * 3 + 1] = w * (truec[l * 3 + 1] - m1);
        g_wt3[l * 3 + 2] = w * (truec[l * 3 + 2] - m2);
        g_wf[l] = w;
    }
}

// ---------------- kernel B: per-sample covariance (pipelined stream) ----------------
#define RES_ACC(wv, px, py, pz, tx, ty, tz) do { \
    S00 = fmaf((px), (tx), S00); S01 = fmaf((px), (ty), S01); S02 = fmaf((px), (tz), S02); \
    S10 = fmaf((py), (tx), S10); S11 = fmaf((py), (ty), S11); S12 = fmaf((py), (tz), S12); \
    S20 = fmaf((pz), (tx), S20); S21 = fmaf((pz), (ty), S21); S22 = fmaf((pz), (tz), S22); \
    P0 = fmaf((wv), (px), P0); P1 = fmaf((wv), (py), P1); P2 = fmaf((wv), (pz), P2); } while (0)

#define COV_COMP(B_) do { \
    RES_ACC((B_).w.x, (B_).p0.x, (B_).p0.y, (B_).p0.z, (B_).t0.x, (B_).t0.y, (B_).t0.z); \
    RES_ACC((B_).w.y, (B_).p0.w, (B_).p1.x, (B_).p1.y, (B_).t0.w, (B_).t1.x, (B_).t1.y); \
    RES_ACC((B_).w.z, (B_).p1.z, (B_).p1.w, (B_).p2.x, (B_).t1.z, (B_).t1.w, (B_).t2.x); \
    RES_ACC((B_).w.w, (B_).p2.y, (B_).p2.z, (B_).p2.w, (B_).t2.y, (B_).t2.z, (B_).t2.w); } while (0)

__global__ void __launch_bounds__(TPB) k_cov(const float* __restrict__ pred) {
    int s = blockIdx.x;
    int tid = threadIdx.x;
    const float4* __restrict__ p4 = reinterpret_cast<const float4*>(pred + (size_t)s * NR * 3);
    const float4* __restrict__ t4 = reinterpret_cast<const float4*>(g_wt3);
    const float4* __restrict__ w4 = reinterpret_cast<const float4*>(g_wf);

    float S00 = 0, S01 = 0, S02 = 0, S10 = 0, S11 = 0, S12 = 0, S20 = 0, S21 = 0, S22 = 0;
    float P0 = 0, P1 = 0, P2 = 0;

    Batch A, B;
    LOADB(A, 0);
    LOADB(B, 1);
    COV_COMP(A);
    LOADB(A, 2);
    COV_COMP(B);
    LOADB(B, 3);
    COV_COMP(A);
    COV_COMP(B);

    __shared__ float red[12][8];
    int lane = tid & 31, wid = tid >> 5;
    float vals[12] = {S00, S01, S02, S10, S11, S12, S20, S21, S22, P0, P1, P2};
#pragma unroll
    for (int k = 0; k < 12; k++) {
        float v = warpsum(vals[k]);
        if (lane == 0) red[k][wid] = v;
    }
    __syncthreads();
    if (tid < 12) {
        float v = 0.f;
#pragma unroll
        for (int i = 0; i < 8; i++) v += red[tid][i];
        g_S[s * 12 + tid] = v;
    }
}

// ---------------- kernel C: Horn quaternion Kabsch ----------------
__global__ void k_rot() {
    int s = blockIdx.x * blockDim.x + threadIdx.x;
    if (s >= NS) return;

    float Sf[12];
#pragma unroll
    for (int i = 0; i < 12; i++) Sf[i] = g_S[s * 12 + i];
    float Sxx = Sf[0], Sxy = Sf[1], Sxz = Sf[2];
    float Syx = Sf[3], Syy = Sf[4], Syz = Sf[5];
    float Szx = Sf[6], Szy = Sf[7], Szz = Sf[8];

    float A[4][4];
    A[0][0] = Sxx + Syy + Szz; A[0][1] = Syz - Szy;         A[0][2] = Szx - Sxz;         A[0][3] = Sxy - Syx;
    A[1][1] = Sxx - Syy - Szz; A[1][2] = Sxy + Syx;         A[1][3] = Szx + Sxz;
    A[2][2] = -Sxx + Syy - Szz; A[2][3] = Syz + Szy;
    A[3][3] = -Sxx - Syy + Szz;
    A[1][0] = A[0][1]; A[2][0] = A[0][2]; A[3][0] = A[0][3];
    A[2][1] = A[1][2]; A[3][1] = A[1][3]; A[3][2] = A[2][3];

    float V[4][4] = {{1, 0, 0, 0}, {0, 1, 0, 0}, {0, 0, 1, 0}, {0, 0, 0, 1}};

    for (int sweep = 0; sweep < 4; sweep++) {
#pragma unroll
        for (int p = 0; p < 3; p++) {
#pragma unroll
            for (int q = p + 1; q < 4; q++) {
                float apq = A[p][q];
                float scale = fabsf(A[p][p]) + fabsf(A[q][q]);
                if (fabsf(apq) > 1e-12f * scale + 1e-30f) {
                    float theta = (A[q][q] - A[p][p]) / (2.0f * apq);
                    float t = 1.0f / (fabsf(theta) + sqrtf(theta * theta + 1.0f));
                    if (theta < 0.0f) t = -t;
                    float cth = 1.0f / sqrtf(t * t + 1.0f);
                    float sth = t * cth;
#pragma unroll
                    for (int r = 0; r < 4; r++) {
                        float arp = A[r][p], arq = A[r][q];
                        A[r][p] = arp * cth - arq * sth;
                        A[r][q] = arp * sth + arq * cth;
                    }
#pragma unroll
                    for (int r = 0; r < 4; r++) {
                        float apr = A[p][r], aqr = A[q][r];
                        A[p][r] = apr * cth - aqr * sth;
                        A[q][r] = apr * sth + aqr * cth;
                    }
#pragma unroll
                    for (int r = 0; r < 4; r++) {
                        float vrp = V[r][p], vrq = V[r][q];
                        V[r][p] = vrp * cth - vrq * sth;
                        V[r][q] = vrp * sth + vrq * cth;
                    }
                }
            }
        }
    }

    int kk = 0;
    float best = A[0][0];
#pragma unroll
    for (int i = 1; i < 4; i++) if (A[i][i] > best) { best = A[i][i]; kk = i; }
    float q0 = V[0][kk], qx = V[1][kk], qy = V[2][kk], qz = V[3][kk];

    float R[3][3];
    R[0][0] = q0 * q0 + qx * qx - qy * qy - qz * qz;
    R[0][1] = 2.0f * (qx * qy - q0 * qz);
    R[0][2] = 2.0f * (qx * qz + q0 * qy);
    R[1][0] = 2.0f * (qy * qx + q0 * qz);
    R[1][1] = q0 * q0 - qx * qx + qy * qy - qz * qz;
    R[1][2] = 2.0f * (qy * qz - q0 * qx);
    R[2][0] = 2.0f * (qz * qx - q0 * qy);
    R[2][1] = 2.0f * (qz * qy + q0 * qx);
    R[2][2] = q0 * q0 - qx * qx - qy * qy + qz * qz;

    // orientation safeguard
    float Sm[3][3] = {{Sxx, Sxy, Sxz}, {Syx, Syy, Syz}, {Szx, Szy, Szz}};
    float obj = 0.f, objT = 0.f;
#pragma unroll
    for (int i = 0; i < 3; i++)
#pragma unroll
        for (int j = 0; j < 3; j++) {
            obj  += R[i][j] * Sm[j][i];
            objT += R[j][i] * Sm[j][i];
        }
    if (objT > obj) {
#pragma unroll
        for (int i = 0; i < 3; i++)
#pragma unroll
            for (int j = i + 1; j < 3; j++) {
                float tmp = R[i][j]; R[i][j] = R[j][i]; R[j][i] = tmp;
            }
    }

    float invLt = g_stats[4];
    float pm0 = Sf[9] * invLt, pm1 = Sf[10] * invLt, pm2 = Sf[11] * invLt;
    int base = s * 12;
    g_RT[base + 0] = R[0][0]; g_RT[base + 1] = R[0][1]; g_RT[base + 2] = R[0][2];
    g_RT[base + 3] = R[1][0]; g_RT[base + 4] = R[1][1]; g_RT[base + 5] = R[1][2];
    g_RT[base + 6] = R[2][0]; g_RT[base + 7] = R[2][1]; g_RT[base + 8] = R[2][2];
    g_RT[base + 9]  = R[0][0] * pm0 + R[0][1] * pm1 + R[0][2] * pm2;
    g_RT[base + 10] = R[1][0] * pm0 + R[1][1] * pm1 + R[1][2] * pm2;
    g_RT[base + 11] = R[2][0] * pm0 + R[2][1] * pm1 + R[2][2] * pm2;
}

// ---------------- kernel D: per-sample TM score (pipelined stream) ----------------
#define RES_TM(wv, px, py, pz, tx, ty, tz) do { \
    float dx = fmaf(R00, (px), fmaf(R01, (py), fmaf(R02, (pz), -c0))) - (tx); \
    float dy = fmaf(R10, (px), fmaf(R11, (py), fmaf(R12, (pz), -c1))) - (ty); \
    float dz = fmaf(R20, (px), fmaf(R21, (py), fmaf(R22, (pz), -c2))) - (tz); \
    float dsq = fmaf(dx, dx, fmaf(dy, dy, dz * dz)); \
    acc += (wv) * rcp_fast(fmaf(dsq, invd0, 1.0f)); } while (0)

#define TM_COMP(B_) do { \
    RES_TM((B_).w.x, (B_).p0.x, (B_).p0.y, (B_).p0.z, (B_).t0.x, (B_).t0.y, (B_).t0.z); \
    RES_TM((B_).w.y, (B_).p0.w, (B_).p1.x, (B_).p1.y, (B_).t0.w, (B_).t1.x, (B_).t1.y); \
    RES_TM((B_).w.z, (B_).p1.z, (B_).p1.w, (B_).p2.x, (B_).t1.z, (B_).t1.w, (B_).t2.x); \
    RES_TM((B_).w.w, (B_).p2.y, (B_).p2.z, (B_).p2.w, (B_).t2.y, (B_).t2.z, (B_).t2.w); } while (0)

__global__ void __launch_bounds__(TPB) k_tm(const float* __restrict__ pred,
                                            float* __restrict__ out) {
    int s = blockIdx.x;
    int tid = threadIdx.x;
    __shared__ float P[16];
    if (tid < 12) P[tid] = g_RT[s * 12 + tid];
    if (tid == 12) P[12] = g_stats[5];
    if (tid == 13) P[13] = g_stats[4];

    const float4* __restrict__ p4 = reinterpret_cast<const float4*>(pred + (size_t)s * NR * 3);
    const float4* __restrict__ t4 = reinterpret_cast<const float4*>(g_wt3);
    const float4* __restrict__ w4 = reinterpret_cast<const float4*>(g_wf);

    Batch A, B;
    LOADB(A, 0);
    LOADB(B, 1);
    __syncthreads();
    float R00 = P[0], R01 = P[1], R02 = P[2];
    float R10 = P[3], R11 = P[4], R12 = P[5];
    float R20 = P[6], R21 = P[7], R22 = P[8];
    float c0 = P[9], c1 = P[10], c2 = P[11];
    float invd0 = P[12], invLt = P[13];

    float acc = 0.f;
    TM_COMP(A);
    LOADB(A, 2);
    TM_COMP(B);
    LOADB(B, 3);
    TM_COMP(A);
    TM_COMP(B);

    __shared__ float red[8];
    int lane = tid & 31, wid = tid >> 5;
    acc = warpsum(acc);
    if (lane == 0) red[wid] = acc;
    __syncthreads();
    if (tid == 0) {
        float v = 0.f;
#pragma unroll
        for (int i = 0; i < 8; i++) v += red[i];
        out[s] = v * invLt;
    }
}

// ---------------- launch ----------------
extern "C" void kernel_launch(void* const* d_in, const int* in_sizes, int n_in,
                              void* d_out, int out_size) {
    const float* pred = (const float*)d_in[0];
    const float* truec = (const float*)d_in[1];
    const int* mask = (const int*)d_in[2];
    float* out = (float*)d_out;

    k_pre<<<1, PRE_T>>>(truec, mask);
    k_cov<<<NS, TPB>>>(pred);
    k_rot<<<4, 256>>>();
    k_tm<<<NS, TPB>>>(pred, out);
}